// round 3
// baseline (speedup 1.0000x reference)
#include <cuda_runtime.h>
#include <cstdint>

#define N_NODES 100000
#define N_EDGES 1000000
#define H 128

// Scratch: per-node transformed features (u = W1_src*z_src + b1, v = W1_dst*z_dst)
__device__ float g_u[(size_t)N_NODES * H];
__device__ float g_v[(size_t)N_NODES * H];

#define MT 64
#define NT 128
#define KT 32

// Tiled fp32 GEMM: out[i,n] = sum_k A[i,k] * W[n, koff+k]  (W row stride 256)
// blockIdx.y == 0: A=z_src, koff=0,  out=g_u (+ b1 folded in)
// blockIdx.y == 1: A=z_dst, koff=128, out=g_v
__global__ __launch_bounds__(256)
void node_gemm_kernel(const float* __restrict__ zsrc,
                      const float* __restrict__ zdst,
                      const float* __restrict__ W1,
                      const float* __restrict__ b1)
{
    __shared__ float As[MT][KT + 1];
    __shared__ float Bs[NT][KT + 1];

    const int tid = threadIdx.x;
    const int tx = tid & 15;        // 0..15 -> n block of 8
    const int ty = tid >> 4;        // 0..15 -> m block of 4
    const int m0 = ty * 4;
    const int n0 = tx * 8;
    const int mbase = blockIdx.x * MT;
    const bool is_src = (blockIdx.y == 0);
    const float* __restrict__ A = is_src ? zsrc : zdst;
    const float* __restrict__ W = W1 + (is_src ? 0 : H);
    float* __restrict__ out = is_src ? g_u : g_v;

    float acc[4][8];
    #pragma unroll
    for (int i = 0; i < 4; ++i)
        #pragma unroll
        for (int j = 0; j < 8; ++j)
            acc[i][j] = 0.f;

    for (int k0 = 0; k0 < H; k0 += KT) {
        // Stage A tile: MT x KT (coalesced global reads, row-major smem)
        #pragma unroll
        for (int l = 0; l < (MT * KT) / 256; ++l) {
            int idx = tid + l * 256;
            int m = idx >> 5;
            int k = idx & 31;
            int mg = mbase + m;
            As[m][k] = (mg < N_NODES) ? A[(size_t)mg * H + (k0 + k)] : 0.f;
        }
        // Stage B tile: NT x KT (W rows have stride 2H = 256)
        #pragma unroll
        for (int l = 0; l < (NT * KT) / 256; ++l) {
            int idx = tid + l * 256;
            int n = idx >> 5;
            int k = idx & 31;
            Bs[n][k] = W[(size_t)n * (2 * H) + (k0 + k)];
        }
        __syncthreads();

        #pragma unroll
        for (int kk = 0; kk < KT; ++kk) {
            float a[4], b[8];
            #pragma unroll
            for (int i = 0; i < 4; ++i) a[i] = As[m0 + i][kk];
            #pragma unroll
            for (int j = 0; j < 8; ++j) b[j] = Bs[n0 + j][kk];
            #pragma unroll
            for (int i = 0; i < 4; ++i)
                #pragma unroll
                for (int j = 0; j < 8; ++j)
                    acc[i][j] = fmaf(a[i], b[j], acc[i][j]);
        }
        __syncthreads();
    }

    // Epilogue: fold bias into u so the edge kernel skips it
    #pragma unroll
    for (int i = 0; i < 4; ++i) {
        int mg = mbase + m0 + i;
        if (mg < N_NODES) {
            float* orow = out + (size_t)mg * H + n0;
            #pragma unroll
            for (int j = 0; j < 8; ++j) {
                float val = acc[i][j];
                if (is_src) val += b1[n0 + j];
                orow[j] = val;
            }
        }
    }
}

// One warp per edge: out[e] = W2 . relu(u[row[e]] + v[col[e]]) + b2
__global__ __launch_bounds__(256)
void edge_kernel(const int* __restrict__ eidx,
                 const float* __restrict__ W2,
                 const float* __restrict__ b2,
                 float* __restrict__ out)
{
    const int lane = threadIdx.x & 31;
    const int e = (int)((blockIdx.x * blockDim.x + threadIdx.x) >> 5);
    if (e >= N_EDGES) return;

    const float4 w = ((const float4*)W2)[lane];

    const int r = eidx[e];
    const int c = eidx[N_EDGES + e];

    const float4 u = *((const float4*)(g_u + (size_t)r * H) + lane);
    const float4 v = *((const float4*)(g_v + (size_t)c * H) + lane);

    float s = fmaxf(u.x + v.x, 0.f) * w.x
            + fmaxf(u.y + v.y, 0.f) * w.y
            + fmaxf(u.z + v.z, 0.f) * w.z
            + fmaxf(u.w + v.w, 0.f) * w.w;

    #pragma unroll
    for (int off = 16; off; off >>= 1)
        s += __shfl_xor_sync(0xffffffffu, s, off);

    if (lane == 0) out[e] = s + b2[0];
}

extern "C" void kernel_launch(void* const* d_in, const int* in_sizes, int n_in,
                              void* d_out, int out_size)
{
    const float* zsrc = (const float*)d_in[0];
    const float* zdst = (const float*)d_in[1];
    const int*   eidx = (const int*)d_in[2];
    const float* W1   = (const float*)d_in[3];
    const float* b1   = (const float*)d_in[4];
    const float* W2   = (const float*)d_in[5];
    const float* b2   = (const float*)d_in[6];
    float*       out  = (float*)d_out;

    dim3 ggrid((N_NODES + MT - 1) / MT, 2);
    node_gemm_kernel<<<ggrid, 256>>>(zsrc, zdst, W1, b1);

    const int warps_per_block = 256 / 32;
    const int eblocks = (N_EDGES + warps_per_block - 1) / warps_per_block;
    edge_kernel<<<eblocks, 256>>>(eidx, W2, b2, out);
}

// round 4
// speedup vs baseline: 1.9701x; 1.9701x over previous
#include <cuda_runtime.h>
#include <cstdint>

#define N_NODES 100000
#define N_EDGES 1000000
#define H 128

// Scratch: per-node transformed features (u = W1_src*z_src + b1, v = W1_dst*z_dst)
__device__ float g_u[(size_t)N_NODES * H];
__device__ float g_v[(size_t)N_NODES * H];

#define MT 128
#define NT 128
#define KT 32
#define SSTR 130   // float stride of smem rows (even -> 8B aligned; 65 in 64-bit units)

// ---- f32x2 packed helpers (SASS FFMA2 path, PTX-only) ----
__device__ __forceinline__ void ffma2(unsigned long long& d,
                                      unsigned long long a,
                                      unsigned long long b) {
    asm("fma.rn.f32x2 %0, %1, %2, %0;" : "+l"(d) : "l"(a), "l"(b));
}
__device__ __forceinline__ unsigned long long pack2(float x, float y) {
    unsigned long long r;
    asm("mov.b64 %0, {%1, %2};" : "=l"(r) : "f"(x), "f"(y));
    return r;
}
__device__ __forceinline__ void unpack2(unsigned long long v, float& x, float& y) {
    asm("mov.b64 {%0, %1}, %2;" : "=f"(x), "=f"(y) : "l"(v));
}

// Tiled fp32 GEMM using packed f32x2 FMA.
// out[m,n] = sum_k A[m,k] * W[n, koff+k]   (W row stride 2H)
// blockIdx.y == 0: A=z_src, koff=0,   out=g_u (+ b1 folded)
// blockIdx.y == 1: A=z_dst, koff=H,   out=g_v
// Thread (tx,ty), tx=tid&15, ty=tid>>4:
//   rows  m = mbase + 2*ty + 32*g + {0,1},  g=0..3   (8 rows)
//   cols  n = 2*tx + 32*j + {0,1},          j=0..3   (8 cols)
__global__ __launch_bounds__(256)
void node_gemm_kernel(const float* __restrict__ zsrc,
                      const float* __restrict__ zdst,
                      const float* __restrict__ W1,
                      const float* __restrict__ b1)
{
    __shared__ __align__(16) float As[KT][SSTR];   // [k][m]
    __shared__ __align__(16) float Bs[KT][SSTR];   // [k][n]

    const int tid = threadIdx.x;
    const int tx = tid & 15;
    const int ty = tid >> 4;
    const int mbase = blockIdx.x * MT;
    const bool is_src = (blockIdx.y == 0);
    const float* __restrict__ A = is_src ? zsrc : zdst;
    const float* __restrict__ W = W1 + (is_src ? 0 : H);
    float* __restrict__ out = is_src ? g_u : g_v;

    unsigned long long acc[8][4];
    #pragma unroll
    for (int r = 0; r < 8; ++r)
        #pragma unroll
        for (int j = 0; j < 4; ++j)
            acc[r][j] = 0ULL;

    const unsigned long long* As64 = (const unsigned long long*)&As[0][0];
    const unsigned long long* Bs64 = (const unsigned long long*)&Bs[0][0];

    for (int k0 = 0; k0 < H; k0 += KT) {
        // Stage A tile [MT x KT] -> As[k][m]  (coalesced gmem reads)
        #pragma unroll
        for (int l = 0; l < (MT * KT) / 256; ++l) {
            int idx = tid + l * 256;
            int m = idx >> 5;
            int k = idx & 31;
            int mg = mbase + m;
            As[k][m] = (mg < N_NODES) ? A[(size_t)mg * H + (k0 + k)] : 0.f;
        }
        // Stage B tile [NT x KT] -> Bs[k][n]  (W row stride 2H)
        #pragma unroll
        for (int l = 0; l < (NT * KT) / 256; ++l) {
            int idx = tid + l * 256;
            int n = idx >> 5;
            int k = idx & 31;
            Bs[k][n] = W[(size_t)n * (2 * H) + (k0 + k)];
        }
        __syncthreads();

        #pragma unroll 8
        for (int kk = 0; kk < KT; ++kk) {
            // a pairs: rows {2ty+32g, 2ty+32g+1}; 64b bank = (kk*65+ty+16g)%16 = (kk+ty)%16 -> conflict-free
            unsigned long long ap[8];
            #pragma unroll
            for (int g = 0; g < 4; ++g) {
                unsigned long long a2 = As64[kk * (SSTR / 2) + ty + 16 * g];
                float lo, hi;
                unpack2(a2, lo, hi);
                ap[2 * g]     = pack2(lo, lo);
                ap[2 * g + 1] = pack2(hi, hi);
            }
            // b pairs: cols {2tx+32j, 2tx+32j+1}; conflict-free likewise
            unsigned long long bp[4];
            #pragma unroll
            for (int j = 0; j < 4; ++j)
                bp[j] = Bs64[kk * (SSTR / 2) + tx + 16 * j];

            #pragma unroll
            for (int r = 0; r < 8; ++r)
                #pragma unroll
                for (int j = 0; j < 4; ++j)
                    ffma2(acc[r][j], ap[r], bp[j]);
        }
        __syncthreads();
    }

    // Epilogue (fold b1 into u)
    #pragma unroll
    for (int r = 0; r < 8; ++r) {
        int g = r >> 1;
        int m = mbase + 2 * ty + 32 * g + (r & 1);
        if (m < N_NODES) {
            #pragma unroll
            for (int j = 0; j < 4; ++j) {
                int n = 2 * tx + 32 * j;
                float lo, hi;
                unpack2(acc[r][j], lo, hi);
                if (is_src) { lo += b1[n]; hi += b1[n + 1]; }
                float2 val = make_float2(lo, hi);
                *(float2*)&out[(size_t)m * H + n] = val;
            }
        }
    }
}

// 4 edges per warp: out[e] = W2 . relu(u[row[e]] + v[col[e]]) + b2
__global__ __launch_bounds__(256)
void edge_kernel(const int* __restrict__ eidx,
                 const float* __restrict__ W2,
                 const float* __restrict__ b2,
                 float* __restrict__ out)
{
    const int lane = threadIdx.x & 31;
    const int w = (int)((blockIdx.x * blockDim.x + threadIdx.x) >> 5);
    const int e0 = w * 4;
    if (e0 >= N_EDGES) return;

    const float4 wv = ((const float4*)W2)[lane];
    const int4 r4 = *(const int4*)&eidx[e0];
    const int4 c4 = *(const int4*)&eidx[N_EDGES + e0];

    const float4* __restrict__ up = (const float4*)g_u;
    const float4* __restrict__ vp = (const float4*)g_v;

    const float4 u0 = up[(size_t)r4.x * 32 + lane];
    const float4 u1 = up[(size_t)r4.y * 32 + lane];
    const float4 u2 = up[(size_t)r4.z * 32 + lane];
    const float4 u3 = up[(size_t)r4.w * 32 + lane];
    const float4 v0 = vp[(size_t)c4.x * 32 + lane];
    const float4 v1 = vp[(size_t)c4.y * 32 + lane];
    const float4 v2 = vp[(size_t)c4.z * 32 + lane];
    const float4 v3 = vp[(size_t)c4.w * 32 + lane];

    float s0 = fmaxf(u0.x + v0.x, 0.f) * wv.x + fmaxf(u0.y + v0.y, 0.f) * wv.y
             + fmaxf(u0.z + v0.z, 0.f) * wv.z + fmaxf(u0.w + v0.w, 0.f) * wv.w;
    float s1 = fmaxf(u1.x + v1.x, 0.f) * wv.x + fmaxf(u1.y + v1.y, 0.f) * wv.y
             + fmaxf(u1.z + v1.z, 0.f) * wv.z + fmaxf(u1.w + v1.w, 0.f) * wv.w;
    float s2 = fmaxf(u2.x + v2.x, 0.f) * wv.x + fmaxf(u2.y + v2.y, 0.f) * wv.y
             + fmaxf(u2.z + v2.z, 0.f) * wv.z + fmaxf(u2.w + v2.w, 0.f) * wv.w;
    float s3 = fmaxf(u3.x + v3.x, 0.f) * wv.x + fmaxf(u3.y + v3.y, 0.f) * wv.y
             + fmaxf(u3.z + v3.z, 0.f) * wv.z + fmaxf(u3.w + v3.w, 0.f) * wv.w;

    #pragma unroll
    for (int off = 16; off; off >>= 1) {
        s0 += __shfl_xor_sync(0xffffffffu, s0, off);
        s1 += __shfl_xor_sync(0xffffffffu, s1, off);
        s2 += __shfl_xor_sync(0xffffffffu, s2, off);
        s3 += __shfl_xor_sync(0xffffffffu, s3, off);
    }

    if (lane == 0) {
        const float bb = b2[0];
        float4 o = make_float4(s0 + bb, s1 + bb, s2 + bb, s3 + bb);
        *(float4*)&out[e0] = o;
    }
}

extern "C" void kernel_launch(void* const* d_in, const int* in_sizes, int n_in,
                              void* d_out, int out_size)
{
    const float* zsrc = (const float*)d_in[0];
    const float* zdst = (const float*)d_in[1];
    const int*   eidx = (const int*)d_in[2];
    const float* W1   = (const float*)d_in[3];
    const float* b1   = (const float*)d_in[4];
    const float* W2   = (const float*)d_in[5];
    const float* b2   = (const float*)d_in[6];
    float*       out  = (float*)d_out;

    dim3 ggrid((N_NODES + MT - 1) / MT, 2);
    node_gemm_kernel<<<ggrid, 256>>>(zsrc, zdst, W1, b1);

    const int edges_per_block = (256 / 32) * 4;   // 32 edges/block
    const int eblocks = (N_EDGES + edges_per_block - 1) / edges_per_block;
    edge_kernel<<<eblocks, 256>>>(eidx, W2, b2, out);
}